// round 4
// baseline (speedup 1.0000x reference)
#include <cuda_runtime.h>
#include <math.h>

#define BB   64
#define LL   4096
#define RC   64
#define SC   128
#define NBLK 30
#define PITCH 132   // multiple of 4 -> float4-aligned rows

// Static device scratch (allocation-free contract)
__device__ float g_h0[(size_t)BB * LL * RC];
__device__ float g_h1[(size_t)BB * LL * RC];
__device__ float g_skip[(size_t)BB * LL * SC];
__device__ float g_partial[(size_t)BB * 32 * SC];

// ---------------------------------------------------------------------------
__global__ __launch_bounds__(256) void proj_kernel(
    const float* __restrict__ x, const float* __restrict__ w_in,
    const float* __restrict__ b_in, float* __restrict__ h)
{
    int idx = blockIdx.x * 256 + threadIdx.x;
    int oc = idx & 63;
    int l  = (idx >> 6) & (LL - 1);
    int b  = idx >> 18;
    float acc = b_in[oc];
#pragma unroll
    for (int c = 0; c < 8; ++c)
        acc += w_in[oc * 8 + c] * x[((size_t)(b * 8 + c)) * LL + l];
    h[(size_t)idx] = acc;
}

// ---------------------------------------------------------------------------
// One WaveNet block. 512 threads, 128 positions per CTA.
// Conv GEMM k-split across two halves of the CTA; epilogue warp-specialized:
// warps 0-7 res GEMM, warps 8-15 skip GEMM. All GEMM smem loads are float4.
// ---------------------------------------------------------------------------
__global__ __launch_bounds__(512, 1) void block_kernel(
    const float* __restrict__ h_in, float* __restrict__ h_out,
    float* __restrict__ skip,
    const float* __restrict__ wd, const float* __restrict__ bd,
    const float* __restrict__ wr, const float* __restrict__ br,
    const float* __restrict__ ws, const float* __restrict__ bs,
    int d, int first)
{
    extern __shared__ float sm[];
    float* s_cur = sm;                    // [64][PITCH]  h[l]
    float* s_del = s_cur + 64 * PITCH;    // [64][PITCH]  h[l-d]; reused as s-half
    float* s_g   = s_del + 64 * PITCH;    // [64][PITCH]  t-half, then gated
    float* s_wd  = s_g   + 64 * PITCH;    // [(c*2+k)][128]
    float* s_wr  = s_wd + 16384;          // [c][64]
    float* s_ws  = s_wr + 4096;           // [c][128]

    const int tid = threadIdx.x;
    const int b   = blockIdx.y;
    const int l0  = blockIdx.x * 128;

    // ---- stage activations (coalesced gmem) ----
    {
        int c  = tid & 63;
        int p0 = tid >> 6;                // 0..7
        const float* hb = h_in + (size_t)b * LL * 64;
#pragma unroll
        for (int p = p0; p < 128; p += 8) {
            int l = l0 + p;
            s_cur[c * PITCH + p] = hb[(size_t)l * 64 + c];
            int ld = l - d;
            s_del[c * PITCH + p] = (ld >= 0) ? hb[(size_t)ld * 64 + c] : 0.f;
        }
    }
    // ---- stage weights ----
    for (int e = tid; e < 16384; e += 512) {       // wd[(o*64+c)*2+k] -> s_wd[(c*2+k)*128+o]
        int o = e >> 7; int r = e & 127;
        s_wd[r * 128 + o] = wd[e];
    }
    for (int e = tid; e < 4096; e += 512) {        // wr[j*64+c] -> s_wr[c*64+j]
        int j = e >> 6, c = e & 63;
        s_wr[c * 64 + j] = wr[e];
    }
    for (int e = tid; e < 8192; e += 512) {        // ws[s*64+c] -> s_ws[c*128+s]
        int s = e >> 6, c = e & 63;
        s_ws[c * 128 + s] = ws[e];
    }
    __syncthreads();

    // ---- conv GEMM: 128 pos x 128 out, k-split in two halves ----
    const int kh = tid >> 8;             // 0 or 1 (warps 0-7 vs 8-15)
    const int r  = tid & 255;
    const int pt = r >> 4, ot = r & 15;
    const int pb = pt * 8, ob = ot * 8;

    float acc[8][8];
#pragma unroll
    for (int p = 0; p < 8; p++)
#pragma unroll
        for (int o = 0; o < 8; o++) acc[p][o] = 0.f;

    const int kbeg = kh * 32;
#pragma unroll 4
    for (int k = kbeg; k < kbeg + 32; ++k) {
        float4 xc0 = *(const float4*)(s_cur + k * PITCH + pb);
        float4 xc1 = *(const float4*)(s_cur + k * PITCH + pb + 4);
        float4 xd0 = *(const float4*)(s_del + k * PITCH + pb);
        float4 xd1 = *(const float4*)(s_del + k * PITCH + pb + 4);
        const float* wp = s_wd + k * 256 + ob;
        float4 wa0 = *(const float4*)(wp);
        float4 wa1 = *(const float4*)(wp + 4);
        float4 wb0 = *(const float4*)(wp + 128);
        float4 wb1 = *(const float4*)(wp + 132);
        float xcv[8] = {xc0.x, xc0.y, xc0.z, xc0.w, xc1.x, xc1.y, xc1.z, xc1.w};
        float xdv[8] = {xd0.x, xd0.y, xd0.z, xd0.w, xd1.x, xd1.y, xd1.z, xd1.w};
        float w0v[8] = {wa0.x, wa0.y, wa0.z, wa0.w, wa1.x, wa1.y, wa1.z, wa1.w};
        float w1v[8] = {wb0.x, wb0.y, wb0.z, wb0.w, wb1.x, wb1.y, wb1.z, wb1.w};
#pragma unroll
        for (int p = 0; p < 8; p++)
#pragma unroll
            for (int o = 0; o < 8; o++)
                acc[p][o] += xdv[p] * w0v[o] + xcv[p] * w1v[o];
    }
    __syncthreads();   // all conv reads of s_del done -> reusable

    // ---- combine k-halves + scatter: t-half -> s_g, s-half -> s_del ----
    {
        float* dst = (ob < 64) ? s_g : s_del;
        int oo = ob & 63;
        if (kh == 0) {
#pragma unroll
            for (int o = 0; o < 8; o++) {
                float bias = bd[ob + o];
#pragma unroll
                for (int p = 0; p < 8; p++)
                    dst[(oo + o) * PITCH + pb + p] = acc[p][o] + bias;
            }
        }
        __syncthreads();
        if (kh == 1) {
#pragma unroll
            for (int o = 0; o < 8; o++)
#pragma unroll
                for (int p = 0; p < 8; p++)
                    dst[(oo + o) * PITCH + pb + p] += acc[p][o];
        }
    }
    __syncthreads();

    // ---- gated = tanh(t) * sigmoid(s) ----
    {
        int c  = tid & 63;
        int p0 = tid >> 6;
#pragma unroll
        for (int p = p0; p < 128; p += 8) {
            float t = s_g[c * PITCH + p];
            float s = s_del[c * PITCH + p];
            s_g[c * PITCH + p] = tanhf(t) * (1.f / (1.f + expf(-s)));
        }
    }
    __syncthreads();

    if (tid < 256) {
        // ---- res GEMM: 128 pos x 64 out, 8x4 tiles, full k ----
        const int j0 = ot * 4;
        float racc[8][4];
#pragma unroll
        for (int p = 0; p < 8; p++)
#pragma unroll
            for (int j = 0; j < 4; j++) racc[p][j] = 0.f;
#pragma unroll 4
        for (int k = 0; k < 64; k++) {
            float4 g0 = *(const float4*)(s_g + k * PITCH + pb);
            float4 g1 = *(const float4*)(s_g + k * PITCH + pb + 4);
            float4 w  = *(const float4*)(s_wr + k * 64 + j0);
            float gv[8] = {g0.x, g0.y, g0.z, g0.w, g1.x, g1.y, g1.z, g1.w};
            float wv[4] = {w.x, w.y, w.z, w.w};
#pragma unroll
            for (int p = 0; p < 8; p++)
#pragma unroll
                for (int j = 0; j < 4; j++) racc[p][j] += gv[p] * wv[j];
        }
        float4 bj = *(const float4*)(br + j0);
        float bv[4] = {bj.x, bj.y, bj.z, bj.w};
#pragma unroll
        for (int p = 0; p < 8; p++) {
            int l = l0 + pb + p;
            float4 v;
            v.x = racc[p][0] + bv[0] + s_cur[(j0 + 0) * PITCH + pb + p];
            v.y = racc[p][1] + bv[1] + s_cur[(j0 + 1) * PITCH + pb + p];
            v.z = racc[p][2] + bv[2] + s_cur[(j0 + 2) * PITCH + pb + p];
            v.w = racc[p][3] + bv[3] + s_cur[(j0 + 3) * PITCH + pb + p];
            *reinterpret_cast<float4*>(&h_out[((size_t)b * LL + l) * 64 + j0]) = v;
        }
    } else {
        // ---- skip GEMM: 128 pos x 128 out, 8x8 tiles, full k, global RMW ----
        const int s0 = ob;
        float sacc[8][8];
#pragma unroll
        for (int p = 0; p < 8; p++) {
            size_t base = ((size_t)b * LL + l0 + pb + p) * 128 + s0;
            if (first) {
#pragma unroll
                for (int o = 0; o < 8; o++) sacc[p][o] = bs[s0 + o];
            } else {
                float4 a  = *reinterpret_cast<const float4*>(&skip[base]);
                float4 a2 = *reinterpret_cast<const float4*>(&skip[base + 4]);
                sacc[p][0] = a.x  + bs[s0 + 0]; sacc[p][1] = a.y  + bs[s0 + 1];
                sacc[p][2] = a.z  + bs[s0 + 2]; sacc[p][3] = a.w  + bs[s0 + 3];
                sacc[p][4] = a2.x + bs[s0 + 4]; sacc[p][5] = a2.y + bs[s0 + 5];
                sacc[p][6] = a2.z + bs[s0 + 6]; sacc[p][7] = a2.w + bs[s0 + 7];
            }
        }
#pragma unroll 4
        for (int k = 0; k < 64; k++) {
            float4 g0 = *(const float4*)(s_g + k * PITCH + pb);
            float4 g1 = *(const float4*)(s_g + k * PITCH + pb + 4);
            float4 w0 = *(const float4*)(s_ws + k * 128 + s0);
            float4 w1 = *(const float4*)(s_ws + k * 128 + s0 + 4);
            float gv[8] = {g0.x, g0.y, g0.z, g0.w, g1.x, g1.y, g1.z, g1.w};
            float wv[8] = {w0.x, w0.y, w0.z, w0.w, w1.x, w1.y, w1.z, w1.w};
#pragma unroll
            for (int p = 0; p < 8; p++)
#pragma unroll
                for (int o = 0; o < 8; o++) sacc[p][o] += gv[p] * wv[o];
        }
#pragma unroll
        for (int p = 0; p < 8; p++) {
            size_t base = ((size_t)b * LL + l0 + pb + p) * 128 + s0;
            float4 v;  v.x  = sacc[p][0]; v.y  = sacc[p][1]; v.z  = sacc[p][2]; v.w  = sacc[p][3];
            float4 v2; v2.x = sacc[p][4]; v2.y = sacc[p][5]; v2.z = sacc[p][6]; v2.w = sacc[p][7];
            *reinterpret_cast<float4*>(&skip[base])     = v;
            *reinterpret_cast<float4*>(&skip[base + 4]) = v2;
        }
    }
}

// ---------------------------------------------------------------------------
// Post: relu(skip) -> out1 -> relu -> out2 -> per-tile column sums
// ---------------------------------------------------------------------------
__global__ __launch_bounds__(256) void post_kernel(
    const float* __restrict__ skip,
    const float* __restrict__ w1g, const float* __restrict__ b1,
    const float* __restrict__ w2g, const float* __restrict__ b2,
    float* __restrict__ partial)
{
    extern __shared__ float sm[];
    float* s_r0  = sm;                     // [128][PITCH]
    float* s_t1  = s_r0 + 128 * PITCH;     // [128][PITCH]
    float* s_w   = s_t1 + 128 * PITCH;     // [128][128]
    float* s_red = s_w + 16384;            // [16][128]

    const int tid = threadIdx.x;
    const int b   = blockIdx.y;
    const int l0  = blockIdx.x * 128;

    {
        int c  = tid & 127;
        int p0 = tid >> 7;
        for (int p = p0; p < 128; p += 2) {
            float v = skip[((size_t)b * LL + l0 + p) * 128 + c];
            s_r0[c * PITCH + p] = fmaxf(v, 0.f);
        }
    }
    for (int e = tid; e < 16384; e += 256) {
        int o = e >> 7, c = e & 127;
        s_w[c * 128 + o] = w1g[e];
    }
    __syncthreads();

    const int pt = tid >> 4, ot = tid & 15;
    const int pb = pt * 8, ob = ot * 8;

    float acc[8][8];
#pragma unroll
    for (int p = 0; p < 8; p++)
#pragma unroll
        for (int o = 0; o < 8; o++) acc[p][o] = 0.f;
#pragma unroll 4
    for (int k = 0; k < 128; k++) {
        float4 g0 = *(const float4*)(s_r0 + k * PITCH + pb);
        float4 g1 = *(const float4*)(s_r0 + k * PITCH + pb + 4);
        float4 w0 = *(const float4*)(s_w + k * 128 + ob);
        float4 w1 = *(const float4*)(s_w + k * 128 + ob + 4);
        float gv[8] = {g0.x, g0.y, g0.z, g0.w, g1.x, g1.y, g1.z, g1.w};
        float wv[8] = {w0.x, w0.y, w0.z, w0.w, w1.x, w1.y, w1.z, w1.w};
#pragma unroll
        for (int p = 0; p < 8; p++)
#pragma unroll
            for (int o = 0; o < 8; o++) acc[p][o] += gv[p] * wv[o];
    }
    __syncthreads();
#pragma unroll
    for (int o = 0; o < 8; o++) {
        float bias = b1[ob + o];
#pragma unroll
        for (int p = 0; p < 8; p++)
            s_t1[(ob + o) * PITCH + pb + p] = fmaxf(acc[p][o] + bias, 0.f);
    }
    __syncthreads();
    for (int e = tid; e < 16384; e += 256) {
        int o = e >> 7, c = e & 127;
        s_w[c * 128 + o] = w2g[e];
    }
    __syncthreads();

    float acc2[8][8];
#pragma unroll
    for (int p = 0; p < 8; p++)
#pragma unroll
        for (int o = 0; o < 8; o++) acc2[p][o] = 0.f;
#pragma unroll 4
    for (int k = 0; k < 128; k++) {
        float4 g0 = *(const float4*)(s_t1 + k * PITCH + pb);
        float4 g1 = *(const float4*)(s_t1 + k * PITCH + pb + 4);
        float4 w0 = *(const float4*)(s_w + k * 128 + ob);
        float4 w1 = *(const float4*)(s_w + k * 128 + ob + 4);
        float gv[8] = {g0.x, g0.y, g0.z, g0.w, g1.x, g1.y, g1.z, g1.w};
        float wv[8] = {w0.x, w0.y, w0.z, w0.w, w1.x, w1.y, w1.z, w1.w};
#pragma unroll
        for (int p = 0; p < 8; p++)
#pragma unroll
            for (int o = 0; o < 8; o++) acc2[p][o] += gv[p] * wv[o];
    }
#pragma unroll
    for (int o = 0; o < 8; o++) {
        float s = 0.f;
#pragma unroll
        for (int p = 0; p < 8; p++) s += acc2[p][o];
        s_red[pt * 128 + ob + o] = s;
    }
    __syncthreads();
    if (tid < 128) {
        float sum = 0.f;
        for (int t = 0; t < 16; t++) sum += s_red[t * 128 + tid];
        partial[((size_t)b * 32 + blockIdx.x) * 128 + tid] = sum + 128.f * b2[tid];
    }
}

// ---------------------------------------------------------------------------
__global__ __launch_bounds__(256) void final_kernel(
    const float* __restrict__ partial,
    const float* __restrict__ wf1, const float* __restrict__ bf1,
    const float* __restrict__ wf2, const float* __restrict__ bf2,
    const float* __restrict__ wf3, const float* __restrict__ bf3,
    float* __restrict__ out)
{
    __shared__ float pooled[128];
    __shared__ float z1[256];
    __shared__ float z2[128];
    int b = blockIdx.x, tid = threadIdx.x;
    if (tid < 128) {
        float s = 0.f;
        for (int t = 0; t < 32; t++) s += partial[((size_t)b * 32 + t) * 128 + tid];
        pooled[tid] = s * (1.f / (float)LL);
    }
    __syncthreads();
    {
        float a = bf1[tid];
        for (int c = 0; c < 128; c++) a += wf1[tid * 128 + c] * pooled[c];
        z1[tid] = fmaxf(a, 0.f);
    }
    __syncthreads();
    if (tid < 128) {
        float a = bf2[tid];
        for (int c = 0; c < 256; c++) a += wf2[tid * 256 + c] * z1[c];
        z2[tid] = fmaxf(a, 0.f);
    }
    __syncthreads();
    if (tid < 6) {
        float a = bf3[tid];
        for (int c = 0; c < 128; c++) a += wf3[tid * 128 + c] * z2[c];
        out[b * 6 + tid] = a;
    }
}

// ---------------------------------------------------------------------------
extern "C" void kernel_launch(void* const* d_in, const int* in_sizes, int n_in,
                              void* d_out, int out_size)
{
    const float* x      = (const float*)d_in[0];
    const float* w_in   = (const float*)d_in[1];
    const float* b_in   = (const float*)d_in[2];
    const float* w_dil  = (const float*)d_in[3];
    const float* b_dil  = (const float*)d_in[4];
    const float* w_res  = (const float*)d_in[5];
    const float* b_res  = (const float*)d_in[6];
    const float* w_skip = (const float*)d_in[7];
    const float* b_skip = (const float*)d_in[8];
    const float* w_out1 = (const float*)d_in[9];
    const float* b_out1 = (const float*)d_in[10];
    const float* w_out2 = (const float*)d_in[11];
    const float* b_out2 = (const float*)d_in[12];
    const float* w_fc1  = (const float*)d_in[13];
    const float* b_fc1  = (const float*)d_in[14];
    const float* w_fc2  = (const float*)d_in[15];
    const float* b_fc2  = (const float*)d_in[16];
    const float* w_fc3  = (const float*)d_in[17];
    const float* b_fc3  = (const float*)d_in[18];
    float* out = (float*)d_out;

    float *h0, *h1, *skipb, *partial;
    cudaGetSymbolAddress((void**)&h0,      g_h0);
    cudaGetSymbolAddress((void**)&h1,      g_h1);
    cudaGetSymbolAddress((void**)&skipb,   g_skip);
    cudaGetSymbolAddress((void**)&partial, g_partial);

    const int BLOCK_SMEM = (3 * 64 * PITCH + 16384 + 4096 + 8192) * 4;
    const int POST_SMEM  = (2 * 128 * PITCH + 16384 + 2048) * 4;
    cudaFuncSetAttribute(block_kernel, cudaFuncAttributeMaxDynamicSharedMemorySize, BLOCK_SMEM);
    cudaFuncSetAttribute(post_kernel,  cudaFuncAttributeMaxDynamicSharedMemorySize, POST_SMEM);

    proj_kernel<<<(BB * LL * 64) / 256, 256>>>(x, w_in, b_in, h0);

    dim3 grid(LL / 128, BB);
    const float* hin = h0;
    float* hout = h1;
    for (int i = 0; i < NBLK; ++i) {
        int d = 1 << (i % 10);
        block_kernel<<<grid, 512, BLOCK_SMEM>>>(
            hin, hout, skipb,
            w_dil + (size_t)i * 128 * 64 * 2, b_dil + i * 128,
            w_res + (size_t)i * 64 * 64,      b_res + i * 64,
            w_skip + (size_t)i * 128 * 64,    b_skip + i * 128,
            d, (i == 0) ? 1 : 0);
        const float* t = hout;
        hout = (float*)hin;
        hin = t;
    }

    post_kernel<<<grid, 256, POST_SMEM>>>(skipb, w_out1, b_out1, w_out2, b_out2, partial);
    final_kernel<<<BB, 256>>>(partial, w_fc1, b_fc1, w_fc2, b_fc2, w_fc3, b_fc3, out);
}

// round 5
// speedup vs baseline: 1.3938x; 1.3938x over previous
#include <cuda_runtime.h>
#include <math.h>
#include <stdint.h>

#define BB   64
#define LL   4096
#define RC   64
#define SC   128
#define NBLK 30
#define P    132    // smem pitch (132 mod 32 == 4 -> conflict-free frag loads)
#define PW   68     // weight pitch for res/skip (68 mod 32 == 4)
#define PITCH 129   // post_kernel pitch (unchanged scalar kernel)

// Static device scratch (allocation-free contract)
__device__ float g_h0[(size_t)BB * LL * RC];
__device__ float g_h1[(size_t)BB * LL * RC];
__device__ float g_skip[(size_t)BB * LL * SC];
__device__ float g_partial[(size_t)BB * 32 * SC];

// ---------------------------------------------------------------------------
__device__ __forceinline__ uint32_t f2tf(float f) {
    uint32_t u;
    asm("cvt.rna.tf32.f32 %0, %1;" : "=r"(u) : "f"(f));
    return u;
}
// split v into tf32 hi + tf32 lo
__device__ __forceinline__ void tfsplit(float v, uint32_t& hi, uint32_t& lo) {
    hi = f2tf(v);
    lo = f2tf(v - __uint_as_float(hi));
}
__device__ __forceinline__ void mma_tf32(float* d, const uint32_t* a, const uint32_t* b) {
    asm volatile(
        "mma.sync.aligned.m16n8k8.row.col.f32.tf32.tf32.f32 "
        "{%0,%1,%2,%3}, {%4,%5,%6,%7}, {%8,%9}, {%0,%1,%2,%3};"
        : "+f"(d[0]), "+f"(d[1]), "+f"(d[2]), "+f"(d[3])
        : "r"(a[0]), "r"(a[1]), "r"(a[2]), "r"(a[3]), "r"(b[0]), "r"(b[1]));
}

// ---------------------------------------------------------------------------
__global__ __launch_bounds__(256) void proj_kernel(
    const float* __restrict__ x, const float* __restrict__ w_in,
    const float* __restrict__ b_in, float* __restrict__ h)
{
    int idx = blockIdx.x * 256 + threadIdx.x;
    int oc = idx & 63;
    int l  = (idx >> 6) & (LL - 1);
    int b  = idx >> 18;
    float acc = b_in[oc];
#pragma unroll
    for (int c = 0; c < 8; ++c)
        acc += w_in[oc * 8 + c] * x[((size_t)(b * 8 + c)) * LL + l];
    h[(size_t)idx] = acc;
}

// ---------------------------------------------------------------------------
// One WaveNet block via 3xTF32 mma.sync. 256 threads, 128 positions per CTA.
//  conv: D[128 out][128 pos] = W[128][128] * X[128 k][128 pos]
//        X rows: k = 2c+0 -> h[l-d], k = 2c+1 -> h[l]   (k-major = wd layout)
//  gate, then res D[64][128] and skip D[128][128] over G[64][128].
// ---------------------------------------------------------------------------
__global__ __launch_bounds__(256) void block_kernel(
    const float* __restrict__ h_in, float* __restrict__ h_out,
    float* __restrict__ skip,
    const float* __restrict__ wd, const float* __restrict__ bd,
    const float* __restrict__ wr, const float* __restrict__ br,
    const float* __restrict__ ws, const float* __restrict__ bs,
    int d, int first)
{
    extern __shared__ float sm[];
    float* s_x = sm;              // [128 k][P]   X (fp32); later: skip D staging
    float* s_w = s_x + 128 * P;   // [128 o][P]   conv W; later wr/ws overlay
    float* s_t = s_w + 128 * P;   // [64][P]      conv t-half; later gated G
    float* s_s = s_t + 64 * P;    // [64][P]      conv s-half; later h_out staging

    const int tid  = threadIdx.x;
    const int lane = tid & 31;
    const int w    = tid >> 5;          // warp 0..7
    const int lr   = lane >> 2;         // 0..7
    const int lc   = lane & 3;          // 0..3
    const int b    = blockIdx.y;
    const int l0   = blockIdx.x * 128;

    // ---- stage X (interleaved: row 2c = delayed, row 2c+1 = current) ----
    {
        int c  = tid & 63;
        int p0 = tid >> 6;
        const float* hb = h_in + (size_t)b * LL * 64;
#pragma unroll
        for (int p = p0; p < 128; p += 4) {
            int l = l0 + p, ld = l - d;
            s_x[(2 * c + 1) * P + p] = hb[(size_t)l * 64 + c];
            s_x[(2 * c) * P + p]     = (ld >= 0) ? hb[(size_t)ld * 64 + c] : 0.f;
        }
    }
    // ---- stage conv W: wd[o][c][t] is row-major [o][k], k = 2c+t ----
    for (int e = tid; e < 16384; e += 256) {
        int o = e >> 7, k = e & 127;
        s_w[o * P + k] = wd[e];
    }
    __syncthreads();

    // ================= conv GEMM (3xTF32) =================
    const int wrow = w >> 2;            // 0..1 -> out half
    const int wcol = w & 3;             // 0..3 -> pos quarter
    const int out0 = wrow * 64;
    const int pos0 = wcol * 32;

    float acc[4][4][4];
#pragma unroll
    for (int ma = 0; ma < 4; ma++)
#pragma unroll
        for (int na = 0; na < 4; na++)
#pragma unroll
            for (int r = 0; r < 4; r++) acc[ma][na][r] = 0.f;

#pragma unroll 1
    for (int ks = 0; ks < 16; ks++) {
        const int kk = ks * 8;
        uint32_t ah[4][4], al[4][4], bh[4][2], bl[4][2];
#pragma unroll
        for (int ma = 0; ma < 4; ma++) {
            const float* base = s_w + (size_t)(out0 + ma * 16 + lr) * P + kk + lc;
            tfsplit(base[0],         ah[ma][0], al[ma][0]);
            tfsplit(base[8 * P],     ah[ma][1], al[ma][1]);
            tfsplit(base[4],         ah[ma][2], al[ma][2]);
            tfsplit(base[8 * P + 4], ah[ma][3], al[ma][3]);
        }
#pragma unroll
        for (int na = 0; na < 4; na++) {
            const float* base = s_x + (size_t)(kk + lc) * P + pos0 + na * 8 + lr;
            tfsplit(base[0],     bh[na][0], bl[na][0]);
            tfsplit(base[4 * P], bh[na][1], bl[na][1]);
        }
#pragma unroll
        for (int ma = 0; ma < 4; ma++)
#pragma unroll
            for (int na = 0; na < 4; na++) {
                mma_tf32(acc[ma][na], ah[ma], bh[na]);
                mma_tf32(acc[ma][na], ah[ma], bl[na]);
                mma_tf32(acc[ma][na], al[ma], bh[na]);
            }
    }
    // epilogue -> s_t (out 0..63) / s_s (out 64..127)
    {
        float* dst = (wrow == 0) ? s_t : s_s;
#pragma unroll
        for (int ma = 0; ma < 4; ma++)
#pragma unroll
            for (int na = 0; na < 4; na++) {
                int row = ma * 16 + lr;
                int col = pos0 + na * 8 + 2 * lc;
                dst[row * P + col]           = acc[ma][na][0];
                dst[row * P + col + 1]       = acc[ma][na][1];
                dst[(row + 8) * P + col]     = acc[ma][na][2];
                dst[(row + 8) * P + col + 1] = acc[ma][na][3];
            }
    }
    __syncthreads();

    // ---- overlay wr/ws into s_w region; gate t,s -> G (into s_t) ----
    float* s_wr = s_w;                 // [64][PW]
    float* s_ws = s_w + 64 * PW;       // [128][PW]
    for (int e = tid; e < 4096; e += 256) {
        int j = e >> 6, c = e & 63;
        s_wr[j * PW + c] = wr[e];
    }
    for (int e = tid; e < 8192; e += 256) {
        int s = e >> 6, c = e & 63;
        s_ws[s * PW + c] = ws[e];
    }
    {
        int c  = tid & 63;
        int p0 = tid >> 6;
        float bt = bd[c], bsg = bd[64 + c];
#pragma unroll
        for (int p = p0; p < 128; p += 4) {
            float t = s_t[c * P + p] + bt;
            float s = s_s[c * P + p] + bsg;
            s_t[c * P + p] = tanhf(t) * (1.f / (1.f + expf(-s)));
        }
    }
    __syncthreads();

    // ================= res GEMM: D[64][128] = wr * G =================
    {
        const int o0  = (w & 3) * 16;
        const int pp0 = (w >> 2) * 64;
        float racc[8][4];
#pragma unroll
        for (int na = 0; na < 8; na++)
#pragma unroll
            for (int r = 0; r < 4; r++) racc[na][r] = 0.f;

#pragma unroll 1
        for (int ks = 0; ks < 8; ks++) {
            const int kk = ks * 8;
            uint32_t ah[4], al[4], bh[8][2], bl[8][2];
            const float* abase = s_wr + (size_t)(o0 + lr) * PW + kk + lc;
            tfsplit(abase[0],          ah[0], al[0]);
            tfsplit(abase[8 * PW],     ah[1], al[1]);
            tfsplit(abase[4],          ah[2], al[2]);
            tfsplit(abase[8 * PW + 4], ah[3], al[3]);
#pragma unroll
            for (int na = 0; na < 8; na++) {
                const float* bbase = s_t + (size_t)(kk + lc) * P + pp0 + na * 8 + lr;
                tfsplit(bbase[0],     bh[na][0], bl[na][0]);
                tfsplit(bbase[4 * P], bh[na][1], bl[na][1]);
            }
#pragma unroll
            for (int na = 0; na < 8; na++) {
                mma_tf32(racc[na], ah, bh[na]);
                mma_tf32(racc[na], ah, bl[na]);
                mma_tf32(racc[na], al, bh[na]);
            }
        }
        // epilogue: + bias + residual (h = s_x row 2o+1) -> s_s[out][pos]
        float br0 = br[o0 + lr], br8 = br[o0 + lr + 8];
#pragma unroll
        for (int na = 0; na < 8; na++) {
            int row = o0 + lr;
            int col = pp0 + na * 8 + 2 * lc;
            s_s[row * P + col]           = racc[na][0] + br0 + s_x[(2 * row + 1) * P + col];
            s_s[row * P + col + 1]       = racc[na][1] + br0 + s_x[(2 * row + 1) * P + col + 1];
            s_s[(row + 8) * P + col]     = racc[na][2] + br8 + s_x[(2 * (row + 8) + 1) * P + col];
            s_s[(row + 8) * P + col + 1] = racc[na][3] + br8 + s_x[(2 * (row + 8) + 1) * P + col + 1];
        }
    }
    __syncthreads();

    // ---- coalesced h_out store ----
    {
        int c  = tid & 63;
        int p0 = tid >> 6;
#pragma unroll
        for (int p = p0; p < 128; p += 4)
            h_out[((size_t)b * LL + l0 + p) * 64 + c] = s_s[c * P + p];
    }

    // ================= skip GEMM: D[128][128] = ws * G =================
    {
        const int o0  = (w & 3) * 32;
        const int pp0 = (w >> 2) * 64;
        float sacc[2][8][4];
#pragma unroll
        for (int ma = 0; ma < 2; ma++)
#pragma unroll
            for (int na = 0; na < 8; na++)
#pragma unroll
                for (int r = 0; r < 4; r++) sacc[ma][na][r] = 0.f;

#pragma unroll 1
        for (int ks = 0; ks < 8; ks++) {
            const int kk = ks * 8;
            uint32_t ah[2][4], al[2][4], bh[8][2], bl[8][2];
#pragma unroll
            for (int ma = 0; ma < 2; ma++) {
                const float* abase = s_ws + (size_t)(o0 + ma * 16 + lr) * PW + kk + lc;
                tfsplit(abase[0],          ah[ma][0], al[ma][0]);
                tfsplit(abase[8 * PW],     ah[ma][1], al[ma][1]);
                tfsplit(abase[4],          ah[ma][2], al[ma][2]);
                tfsplit(abase[8 * PW + 4], ah[ma][3], al[ma][3]);
            }
#pragma unroll
            for (int na = 0; na < 8; na++) {
                const float* bbase = s_t + (size_t)(kk + lc) * P + pp0 + na * 8 + lr;
                tfsplit(bbase[0],     bh[na][0], bl[na][0]);
                tfsplit(bbase[4 * P], bh[na][1], bl[na][1]);
            }
#pragma unroll
            for (int ma = 0; ma < 2; ma++)
#pragma unroll
                for (int na = 0; na < 8; na++) {
                    mma_tf32(sacc[ma][na], ah[ma], bh[na]);
                    mma_tf32(sacc[ma][na], ah[ma], bl[na]);
                    mma_tf32(sacc[ma][na], al[ma], bh[na]);
                }
        }
        // epilogue -> stage into s_x region as [s][pos]
#pragma unroll
        for (int ma = 0; ma < 2; ma++)
#pragma unroll
            for (int na = 0; na < 8; na++) {
                int row = o0 + ma * 16 + lr;
                int col = pp0 + na * 8 + 2 * lc;
                s_x[row * P + col]           = sacc[ma][na][0];
                s_x[row * P + col + 1]       = sacc[ma][na][1];
                s_x[(row + 8) * P + col]     = sacc[ma][na][2];
                s_x[(row + 8) * P + col + 1] = sacc[ma][na][3];
            }
    }
    __syncthreads();

    // ---- coalesced skip RMW ----
    {
        int s  = tid & 127;
        int pr = tid >> 7;
        float bsv = bs[s];
#pragma unroll
        for (int p = pr; p < 128; p += 2) {
            size_t gi = ((size_t)b * LL + l0 + p) * 128 + s;
            float v = s_x[s * P + p] + bsv;
            if (!first) v += skip[gi];
            skip[gi] = v;
        }
    }
}

// ---------------------------------------------------------------------------
// Post: relu(skip) -> out1 -> relu -> out2 -> per-tile column sums (scalar)
// ---------------------------------------------------------------------------
__global__ __launch_bounds__(256) void post_kernel(
    const float* __restrict__ skip,
    const float* __restrict__ w1g, const float* __restrict__ b1,
    const float* __restrict__ w2g, const float* __restrict__ b2,
    float* __restrict__ partial)
{
    extern __shared__ float sm[];
    float* s_r0  = sm;                     // [128][PITCH]
    float* s_t1  = s_r0 + 128 * PITCH;     // [128][PITCH]
    float* s_w   = s_t1 + 128 * PITCH;     // [128][128]
    float* s_red = s_w + 16384;            // [16][128]

    const int tid = threadIdx.x;
    const int b   = blockIdx.y;
    const int l0  = blockIdx.x * 128;

    {
        int c  = tid & 127;
        int p0 = tid >> 7;
        for (int p = p0; p < 128; p += 2) {
            float v = skip[((size_t)b * LL + l0 + p) * 128 + c];
            s_r0[c * PITCH + p] = fmaxf(v, 0.f);
        }
    }
    for (int e = tid; e < 16384; e += 256) {
        int o = e >> 7, c = e & 127;
        s_w[c * 128 + o] = w1g[e];
    }
    __syncthreads();

    const int pt = tid >> 4, ot = tid & 15;
    const int pb = pt * 8, ob = ot * 8;

    float acc[8][8];
#pragma unroll
    for (int p = 0; p < 8; p++)
#pragma unroll
        for (int o = 0; o < 8; o++) acc[p][o] = 0.f;
#pragma unroll 4
    for (int k = 0; k < 128; k++) {
        float gv[8], wv[8];
#pragma unroll
        for (int p = 0; p < 8; p++) gv[p] = s_r0[k * PITCH + pb + p];
#pragma unroll
        for (int o = 0; o < 8; o++) wv[o] = s_w[k * 128 + ob + o];
#pragma unroll
        for (int p = 0; p < 8; p++)
#pragma unroll
            for (int o = 0; o < 8; o++) acc[p][o] += gv[p] * wv[o];
    }
    __syncthreads();
#pragma unroll
    for (int o = 0; o < 8; o++) {
        float bias = b1[ob + o];
#pragma unroll
        for (int p = 0; p < 8; p++)
            s_t1[(ob + o) * PITCH + pb + p] = fmaxf(acc[p][o] + bias, 0.f);
    }
    __syncthreads();
    for (int e = tid; e < 16384; e += 256) {
        int o = e >> 7, c = e & 127;
        s_w[c * 128 + o] = w2g[e];
    }
    __syncthreads();

    float acc2[8][8];
#pragma unroll
    for (int p = 0; p < 8; p++)
#pragma unroll
        for (int o = 0; o < 8; o++) acc2[p][o] = 0.f;
#pragma unroll 4
    for (int k = 0; k < 128; k++) {
        float gv[8], wv[8];
#pragma unroll
        for (int p = 0; p < 8; p++) gv[p] = s_t1[k * PITCH + pb + p];
#pragma unroll
        for (int o = 0; o < 8; o++) wv[o] = s_w[k * 128 + ob + o];
#pragma unroll
        for (int p = 0; p < 8; p++)
#pragma unroll
            for (int o = 0; o < 8; o++) acc2[p][o] += gv[p] * wv[o];
    }
#pragma unroll
    for (int o = 0; o < 8; o++) {
        float s = 0.f;
#pragma unroll
        for (int p = 0; p < 8; p++) s += acc2[p][o];
        s_red[pt * 128 + ob + o] = s;
    }
    __syncthreads();
    if (tid < 128) {
        float sum = 0.f;
        for (int t = 0; t < 16; t++) sum += s_red[t * 128 + tid];
        partial[((size_t)b * 32 + blockIdx.x) * 128 + tid] = sum + 128.f * b2[tid];
    }
}

// ---------------------------------------------------------------------------
__global__ __launch_bounds__(256) void final_kernel(
    const float* __restrict__ partial,
    const float* __restrict__ wf1, const float* __restrict__ bf1,
    const float* __restrict__ wf2, const float* __restrict__ bf2,
    const float* __restrict__ wf3, const float* __restrict__ bf3,
    float* __restrict__ out)
{
    __shared__ float pooled[128];
    __shared__ float z1[256];
    __shared__ float z2[128];
    int b = blockIdx.x, tid = threadIdx.x;
    if (tid < 128) {
        float s = 0.f;
        for (int t = 0; t < 32; t++) s += partial[((size_t)b * 32 + t) * 128 + tid];
        pooled[tid] = s * (1.f / (float)LL);
    }
    __syncthreads();
    {
        float a = bf1[tid];
        for (int c = 0; c < 128; c++) a += wf1[tid * 128 + c] * pooled[c];
        z1[tid] = fmaxf(a, 0.f);
    }
    __syncthreads();
    if (tid < 128) {
        float a = bf2[tid];
        for (int c = 0; c < 256; c++) a += wf2[tid * 256 + c] * z1[c];
        z2[tid] = fmaxf(a, 0.f);
    }
    __syncthreads();
    if (tid < 6) {
        float a = bf3[tid];
        for (int c = 0; c < 128; c++) a += wf3[tid * 128 + c] * z2[c];
        out[b * 6 + tid] = a;
    }
}

// ---------------------------------------------------------------------------
extern "C" void kernel_launch(void* const* d_in, const int* in_sizes, int n_in,
                              void* d_out, int out_size)
{
    const float* x      = (const float*)d_in[0];
    const float* w_in   = (const float*)d_in[1];
    const float* b_in   = (const float*)d_in[2];
    const float* w_dil  = (const float*)d_in[3];
    const float* b_dil  = (const float*)d_in[4];
    const float* w_res  = (const float*)d_in[5];
    const float* b_res  = (const float*)d_in[6];
    const float* w_skip = (const float*)d_in[7];
    const float* b_skip = (const float*)d_in[8];
    const float* w_out1 = (const float*)d_in[9];
    const float* b_out1 = (const float*)d_in[10];
    const float* w_out2 = (const float*)d_in[11];
    const float* b_out2 = (const float*)d_in[12];
    const float* w_fc1  = (const float*)d_in[13];
    const float* b_fc1  = (const float*)d_in[14];
    const float* w_fc2  = (const float*)d_in[15];
    const float* b_fc2  = (const float*)d_in[16];
    const float* w_fc3  = (const float*)d_in[17];
    const float* b_fc3  = (const float*)d_in[18];
    float* out = (float*)d_out;

    float *h0, *h1, *skipb, *partial;
    cudaGetSymbolAddress((void**)&h0,      g_h0);
    cudaGetSymbolAddress((void**)&h1,      g_h1);
    cudaGetSymbolAddress((void**)&skipb,   g_skip);
    cudaGetSymbolAddress((void**)&partial, g_partial);

    const int BLOCK_SMEM = (384 * P) * 4;                          // 202,752 B
    const int POST_SMEM  = (2 * 128 * PITCH + 16384 + 2048) * 4;   // 205,824 B
    cudaFuncSetAttribute(block_kernel, cudaFuncAttributeMaxDynamicSharedMemorySize, BLOCK_SMEM);
    cudaFuncSetAttribute(post_kernel,  cudaFuncAttributeMaxDynamicSharedMemorySize, POST_SMEM);

    proj_kernel<<<(BB * LL * 64) / 256, 256>>>(x, w_in, b_in, h0);

    dim3 grid(LL / 128, BB);
    const float* hin = h0;
    float* hout = h1;
    for (int i = 0; i < NBLK; ++i) {
        int d = 1 << (i % 10);
        block_kernel<<<grid, 256, BLOCK_SMEM>>>(
            hin, hout, skipb,
            w_dil + (size_t)i * 128 * 64 * 2, b_dil + i * 128,
            w_res + (size_t)i * 64 * 64,      b_res + i * 64,
            w_skip + (size_t)i * 128 * 64,    b_skip + i * 128,
            d, (i == 0) ? 1 : 0);
        const float* t = hout;
        hout = (float*)hin;
        hin = t;
    }

    post_kernel<<<grid, 256, POST_SMEM>>>(skipb, w_out1, b_out1, w_out2, b_out2, partial);
    final_kernel<<<BB, 256>>>(partial, w_fc1, b_fc1, w_fc2, b_fc2, w_fc3, b_fc3, out);
}

// round 7
// speedup vs baseline: 1.9108x; 1.3710x over previous
#include <cuda_runtime.h>
#include <cuda_bf16.h>
#include <math.h>
#include <stdint.h>

#define BB   64
#define LL   4096
#define RC   64
#define SC   128
#define NBLK 30
#define P    132    // fp32 staging pitch (floats)
#define PX   68     // pitch (words) for 64-pair split arrays (68 mod 32 == 4)
#define PG   36     // pitch (words) for 32-pair split arrays (36 mod 32 == 4)

// Static device scratch (allocation-free contract)
__device__ float g_h0[(size_t)BB * LL * RC];
__device__ float g_h1[(size_t)BB * LL * RC];
__device__ float g_skip[(size_t)BB * LL * SC];
__device__ float g_partial[(size_t)BB * 32 * SC];

// ---------------------------------------------------------------------------
// Split two fp32 into packed bf16x2 (hi, lo). low16 = first element.
__device__ __forceinline__ void bfsplit2(float v0, float v1, uint32_t& hi, uint32_t& lo) {
    __nv_bfloat16 h0 = __float2bfloat16_rn(v0);
    __nv_bfloat16 h1 = __float2bfloat16_rn(v1);
    float r0 = v0 - __bfloat162float(h0);
    float r1 = v1 - __bfloat162float(h1);
    __nv_bfloat16 l0 = __float2bfloat16_rn(r0);
    __nv_bfloat16 l1 = __float2bfloat16_rn(r1);
    hi = (uint32_t)__bfloat16_as_ushort(h0) | ((uint32_t)__bfloat16_as_ushort(h1) << 16);
    lo = (uint32_t)__bfloat16_as_ushort(l0) | ((uint32_t)__bfloat16_as_ushort(l1) << 16);
}

__device__ __forceinline__ void mma_bf16(float* d, const uint32_t* a, const uint32_t* b) {
    asm volatile(
        "mma.sync.aligned.m16n8k16.row.col.f32.bf16.bf16.f32 "
        "{%0,%1,%2,%3}, {%4,%5,%6,%7}, {%8,%9}, {%0,%1,%2,%3};"
        : "+f"(d[0]), "+f"(d[1]), "+f"(d[2]), "+f"(d[3])
        : "r"(a[0]), "r"(a[1]), "r"(a[2]), "r"(a[3]), "r"(b[0]), "r"(b[1]));
}

// ---------------------------------------------------------------------------
__global__ __launch_bounds__(256) void proj_kernel(
    const float* __restrict__ x, const float* __restrict__ w_in,
    const float* __restrict__ b_in, float* __restrict__ h)
{
    int idx = blockIdx.x * 256 + threadIdx.x;
    int oc = idx & 63;
    int l  = (idx >> 6) & (LL - 1);
    int b  = idx >> 18;
    float acc = b_in[oc];
#pragma unroll
    for (int c = 0; c < 8; ++c)
        acc += w_in[oc * 8 + c] * x[((size_t)(b * 8 + c)) * LL + l];
    h[(size_t)idx] = acc;
}

// ---------------------------------------------------------------------------
// One WaveNet block via 3xBF16 mma.sync (pre-split packed operands).
// 256 threads, 128 positions per CTA.
// ---------------------------------------------------------------------------
__global__ __launch_bounds__(256) void block_kernel(
    const float* __restrict__ h_in, float* __restrict__ h_out,
    float* __restrict__ skip,
    const float* __restrict__ wd, const float* __restrict__ bd,
    const float* __restrict__ wr, const float* __restrict__ br,
    const float* __restrict__ ws, const float* __restrict__ bs,
    int d, int first)
{
    extern __shared__ float sm[];
    float*    s_ts = sm;                            // [128][P] fp32 staging
    uint32_t* s_xh = (uint32_t*)(sm + 128 * P);     // [128 pos][PX] X hi pairs (k pairs)
    uint32_t* s_xl = s_xh + 128 * PX;
    uint32_t* s_wh = s_xl + 128 * PX;               // [128 o][PX] conv W hi pairs
    uint32_t* s_wl = s_wh + 128 * PX;
    // overlays after conv:
    uint32_t* s_gh  = s_xh;                         // [128 pos][PG] gated G pairs (c pairs)
    uint32_t* s_gl  = s_xl;
    uint32_t* s_wrh = s_wh;                         // [64 o][PG]
    uint32_t* s_wrl = s_wl;
    uint32_t* s_wsh = s_wh + 64 * PG;               // [128 o][PG]
    uint32_t* s_wsl = s_wl + 64 * PG;

    const int tid  = threadIdx.x;
    const int lane = tid & 31;
    const int w    = tid >> 5;      // warp 0..7
    const int lr   = lane >> 2;     // 0..7
    const int lc   = lane & 3;      // 0..3
    const int b    = blockIdx.y;
    const int l0   = blockIdx.x * 128;

    // ---- stage X split: pair (k=2c: delayed, k=2c+1: current) ----
    {
        int c = tid & 63, p0 = tid >> 6;
        const float* hb = h_in + (size_t)b * LL * 64;
#pragma unroll
        for (int p = p0; p < 128; p += 4) {
            int l = l0 + p, ld = l - d;
            float cur = hb[(size_t)l * 64 + c];
            float del = (ld >= 0) ? hb[(size_t)ld * 64 + c] : 0.f;
            uint32_t hi, lo; bfsplit2(del, cur, hi, lo);
            s_xh[p * PX + c] = hi; s_xl[p * PX + c] = lo;
        }
    }
    // ---- stage conv W split: wd row-major [o][k], k pairs contiguous ----
    for (int e = tid; e < 8192; e += 256) {
        int o = e >> 6, j = e & 63;
        float2 v = *(const float2*)(wd + o * 128 + 2 * j);
        uint32_t hi, lo; bfsplit2(v.x, v.y, hi, lo);
        s_wh[o * PX + j] = hi; s_wl[o * PX + j] = lo;
    }
    __syncthreads();

    // ================= conv GEMM: D[128 out][128 pos], K=128 =================
    {
        const int out0 = (w >> 2) * 64;
        const int pos0 = (w & 3) * 32;
        float acc[4][4][4];
#pragma unroll
        for (int mt = 0; mt < 4; mt++)
#pragma unroll
            for (int nt = 0; nt < 4; nt++)
#pragma unroll
                for (int r = 0; r < 4; r++) acc[mt][nt][r] = 0.f;

#pragma unroll 1
        for (int ks = 0; ks < 8; ks++) {
            const int kp = ks * 8 + lc;
            uint32_t ah[4][4], al[4][4], bh[4][2], bl[4][2];
#pragma unroll
            for (int mt = 0; mt < 4; mt++) {
                int r0 = (out0 + mt * 16 + lr) * PX + kp;
                int r8 = r0 + 8 * PX;
                ah[mt][0] = s_wh[r0]; ah[mt][1] = s_wh[r8];
                ah[mt][2] = s_wh[r0 + 4]; ah[mt][3] = s_wh[r8 + 4];
                al[mt][0] = s_wl[r0]; al[mt][1] = s_wl[r8];
                al[mt][2] = s_wl[r0 + 4]; al[mt][3] = s_wl[r8 + 4];
            }
#pragma unroll
            for (int nt = 0; nt < 4; nt++) {
                int q = (pos0 + nt * 8 + lr) * PX + kp;
                bh[nt][0] = s_xh[q]; bh[nt][1] = s_xh[q + 4];
                bl[nt][0] = s_xl[q]; bl[nt][1] = s_xl[q + 4];
            }
#pragma unroll
            for (int mt = 0; mt < 4; mt++)
#pragma unroll
                for (int nt = 0; nt < 4; nt++) {
                    mma_bf16(acc[mt][nt], ah[mt], bh[nt]);
                    mma_bf16(acc[mt][nt], ah[mt], bl[nt]);
                    mma_bf16(acc[mt][nt], al[mt], bh[nt]);
                }
        }
#pragma unroll
        for (int mt = 0; mt < 4; mt++)
#pragma unroll
            for (int nt = 0; nt < 4; nt++) {
                int row = out0 + mt * 16 + lr;
                int col = pos0 + nt * 8 + 2 * lc;
                *(float2*)&s_ts[row * P + col] = make_float2(acc[mt][nt][0], acc[mt][nt][1]);
                *(float2*)&s_ts[(row + 8) * P + col] = make_float2(acc[mt][nt][2], acc[mt][nt][3]);
            }
    }
    __syncthreads();

    // ---- stage wr/ws splits (overwrites conv-W region); gate -> G split ----
    for (int e = tid; e < 2048; e += 256) {
        int o = e >> 5, j = e & 31;
        float2 v = *(const float2*)(wr + o * 64 + 2 * j);
        uint32_t hi, lo; bfsplit2(v.x, v.y, hi, lo);
        s_wrh[o * PG + j] = hi; s_wrl[o * PG + j] = lo;
    }
    for (int e = tid; e < 4096; e += 256) {
        int o = e >> 5, j = e & 31;
        float2 v = *(const float2*)(ws + o * 64 + 2 * j);
        uint32_t hi, lo; bfsplit2(v.x, v.y, hi, lo);
        s_wsh[o * PG + j] = hi; s_wsl[o * PG + j] = lo;
    }
    for (int it = w; it < 128; it += 8) {
        int cp = it >> 2, pos = (it & 3) * 32 + lane;
        int c0 = 2 * cp;
        float t0 = s_ts[c0 * P + pos] + bd[c0];
        float t1 = s_ts[(c0 + 1) * P + pos] + bd[c0 + 1];
        float sg0 = s_ts[(64 + c0) * P + pos] + bd[64 + c0];
        float sg1 = s_ts[(65 + c0) * P + pos] + bd[65 + c0];
        float g0 = tanhf(t0) * (1.f / (1.f + expf(-sg0)));
        float g1 = tanhf(t1) * (1.f / (1.f + expf(-sg1)));
        uint32_t hi, lo; bfsplit2(g0, g1, hi, lo);
        s_gh[pos * PG + cp] = hi; s_gl[pos * PG + cp] = lo;
    }
    __syncthreads();

    // ================= res GEMM: D[64][128] = wr * G, K=64 =================
    {
        const int o0  = (w & 3) * 16;
        const int pp0 = (w >> 2) * 64;
        float racc[8][4];
#pragma unroll
        for (int nt = 0; nt < 8; nt++)
#pragma unroll
            for (int r = 0; r < 4; r++) racc[nt][r] = 0.f;

#pragma unroll 1
        for (int ks = 0; ks < 4; ks++) {
            const int kp = ks * 8 + lc;
            uint32_t ah[4], al[4], bh[8][2], bl[8][2];
            int r0 = (o0 + lr) * PG + kp, r8 = r0 + 8 * PG;
            ah[0] = s_wrh[r0]; ah[1] = s_wrh[r8]; ah[2] = s_wrh[r0 + 4]; ah[3] = s_wrh[r8 + 4];
            al[0] = s_wrl[r0]; al[1] = s_wrl[r8]; al[2] = s_wrl[r0 + 4]; al[3] = s_wrl[r8 + 4];
#pragma unroll
            for (int nt = 0; nt < 8; nt++) {
                int q = (pp0 + nt * 8 + lr) * PG + kp;
                bh[nt][0] = s_gh[q]; bh[nt][1] = s_gh[q + 4];
                bl[nt][0] = s_gl[q]; bl[nt][1] = s_gl[q + 4];
            }
#pragma unroll
            for (int nt = 0; nt < 8; nt++) {
                mma_bf16(racc[nt], ah, bh[nt]);
                mma_bf16(racc[nt], ah, bl[nt]);
                mma_bf16(racc[nt], al, bh[nt]);
            }
        }
        float b0v = br[o0 + lr], b8v = br[o0 + lr + 8];
#pragma unroll
        for (int nt = 0; nt < 8; nt++) {
            int row = o0 + lr;
            int col = pp0 + nt * 8 + 2 * lc;
            *(float2*)&s_ts[row * P + col] = make_float2(racc[nt][0] + b0v, racc[nt][1] + b0v);
            *(float2*)&s_ts[(row + 8) * P + col] = make_float2(racc[nt][2] + b8v, racc[nt][3] + b8v);
        }
    }
    __syncthreads();

    // ---- h_out = res + residual(h_in), coalesced ----
    {
        int c = tid & 63, p0 = tid >> 6;
#pragma unroll
        for (int p = p0; p < 128; p += 4) {
            size_t gi = ((size_t)b * LL + l0 + p) * 64 + c;
            h_out[gi] = s_ts[c * P + p] + h_in[gi];
        }
    }
    __syncthreads();

    // ================= skip GEMM: D[128][128] = ws * G, K=64 =================
    {
        const int o0  = (w & 3) * 32;
        const int pp0 = (w >> 2) * 64;
        float sacc[2][8][4];
#pragma unroll
        for (int mt = 0; mt < 2; mt++)
#pragma unroll
            for (int nt = 0; nt < 8; nt++)
#pragma unroll
                for (int r = 0; r < 4; r++) sacc[mt][nt][r] = 0.f;

#pragma unroll 1
        for (int ks = 0; ks < 4; ks++) {
            const int kp = ks * 8 + lc;
            uint32_t ah[2][4], al[2][4], bh[8][2], bl[8][2];
#pragma unroll
            for (int mt = 0; mt < 2; mt++) {
                int r0 = (o0 + mt * 16 + lr) * PG + kp, r8 = r0 + 8 * PG;
                ah[mt][0] = s_wsh[r0]; ah[mt][1] = s_wsh[r8];
                ah[mt][2] = s_wsh[r0 + 4]; ah[mt][3] = s_wsh[r8 + 4];
                al[mt][0] = s_wsl[r0]; al[mt][1] = s_wsl[r8];
                al[mt][2] = s_wsl[r0 + 4]; al[mt][3] = s_wsl[r8 + 4];
            }
#pragma unroll
            for (int nt = 0; nt < 8; nt++) {
                int q = (pp0 + nt * 8 + lr) * PG + kp;
                bh[nt][0] = s_gh[q]; bh[nt][1] = s_gh[q + 4];
                bl[nt][0] = s_gl[q]; bl[nt][1] = s_gl[q + 4];
            }
#pragma unroll
            for (int mt = 0; mt < 2; mt++)
#pragma unroll
                for (int nt = 0; nt < 8; nt++) {
                    mma_bf16(sacc[mt][nt], ah[mt], bh[nt]);
                    mma_bf16(sacc[mt][nt], ah[mt], bl[nt]);
                    mma_bf16(sacc[mt][nt], al[mt], bh[nt]);
                }
        }
#pragma unroll
        for (int mt = 0; mt < 2; mt++)
#pragma unroll
            for (int nt = 0; nt < 8; nt++) {
                int row = o0 + mt * 16 + lr;
                int col = pp0 + nt * 8 + 2 * lc;
                *(float2*)&s_ts[row * P + col] = make_float2(sacc[mt][nt][0], sacc[mt][nt][1]);
                *(float2*)&s_ts[(row + 8) * P + col] = make_float2(sacc[mt][nt][2], sacc[mt][nt][3]);
            }
    }
    __syncthreads();

    // ---- coalesced skip RMW ----
    {
        int s = tid & 127, pr = tid >> 7;
        float bsv = bs[s];
#pragma unroll
        for (int p = pr; p < 128; p += 2) {
            size_t gi = ((size_t)b * LL + l0 + p) * 128 + s;
            float v = s_ts[s * P + p] + bsv;
            if (!first) v += skip[gi];
            skip[gi] = v;
        }
    }
}

// ---------------------------------------------------------------------------
// Post: relu(skip) -> out1 -> relu -> out2 -> per-tile column sums (bf16 mma)
// ---------------------------------------------------------------------------
__global__ __launch_bounds__(256) void post_kernel(
    const float* __restrict__ skip,
    const float* __restrict__ w1g, const float* __restrict__ b1,
    const float* __restrict__ w2g, const float* __restrict__ b2,
    float* __restrict__ partial)
{
    extern __shared__ float sm[];
    float*    s_ts = sm;                          // [128][P] fp32 staging
    uint32_t* s_rh = (uint32_t*)(sm + 128 * P);   // [128 pos][PX] act hi pairs
    uint32_t* s_rl = s_rh + 128 * PX;
    uint32_t* s_wh = s_rl + 128 * PX;             // [128 o][PX] weight hi pairs
    uint32_t* s_wl = s_wh + 128 * PX;

    const int tid  = threadIdx.x;
    const int lane = tid & 31;
    const int w    = tid >> 5;
    const int lr   = lane >> 2;
    const int lc   = lane & 3;
    const int b    = blockIdx.y;
    const int l0   = blockIdx.x * 128;

    const int out0 = (w >> 2) * 64;
    const int pos0 = (w & 3) * 32;

    // ---- stage relu(skip) split + w1 split ----
    {
        int cp = tid & 63, p0 = tid >> 6;
#pragma unroll
        for (int p = p0; p < 128; p += 4) {
            float2 v = *(const float2*)(skip + ((size_t)b * LL + l0 + p) * 128 + 2 * cp);
            v.x = fmaxf(v.x, 0.f); v.y = fmaxf(v.y, 0.f);
            uint32_t hi, lo; bfsplit2(v.x, v.y, hi, lo);
            s_rh[p * PX + cp] = hi; s_rl[p * PX + cp] = lo;
        }
    }
    for (int e = tid; e < 8192; e += 256) {
        int o = e >> 6, j = e & 63;
        float2 v = *(const float2*)(w1g + o * 128 + 2 * j);
        uint32_t hi, lo; bfsplit2(v.x, v.y, hi, lo);
        s_wh[o * PX + j] = hi; s_wl[o * PX + j] = lo;
    }
    __syncthreads();

    // ---- GEMM1: D[128][128] = w1 * r ----
    {
        float acc[4][4][4];
#pragma unroll
        for (int mt = 0; mt < 4; mt++)
#pragma unroll
            for (int nt = 0; nt < 4; nt++)
#pragma unroll
                for (int r = 0; r < 4; r++) acc[mt][nt][r] = 0.f;
#pragma unroll 1
        for (int ks = 0; ks < 8; ks++) {
            const int kp = ks * 8 + lc;
            uint32_t ah[4][4], al[4][4], bh[4][2], bl[4][2];
#pragma unroll
            for (int mt = 0; mt < 4; mt++) {
                int r0 = (out0 + mt * 16 + lr) * PX + kp, r8 = r0 + 8 * PX;
                ah[mt][0] = s_wh[r0]; ah[mt][1] = s_wh[r8];
                ah[mt][2] = s_wh[r0 + 4]; ah[mt][3] = s_wh[r8 + 4];
                al[mt][0] = s_wl[r0]; al[mt][1] = s_wl[r8];
                al[mt][2] = s_wl[r0 + 4]; al[mt][3] = s_wl[r8 + 4];
            }
#pragma unroll
            for (int nt = 0; nt < 4; nt++) {
                int q = (pos0 + nt * 8 + lr) * PX + kp;
                bh[nt][0] = s_rh[q]; bh[nt][1] = s_rh[q + 4];
                bl[nt][0] = s_rl[q]; bl[nt][1] = s_rl[q + 4];
            }
#pragma unroll
            for (int mt = 0; mt < 4; mt++)
#pragma unroll
                for (int nt = 0; nt < 4; nt++) {
                    mma_bf16(acc[mt][nt], ah[mt], bh[nt]);
                    mma_bf16(acc[mt][nt], ah[mt], bl[nt]);
                    mma_bf16(acc[mt][nt], al[mt], bh[nt]);
                }
        }
#pragma unroll
        for (int mt = 0; mt < 4; mt++) {
            int row = out0 + mt * 16 + lr;
            float bv0 = b1[row], bv8 = b1[row + 8];
#pragma unroll
            for (int nt = 0; nt < 4; nt++) {
                int col = pos0 + nt * 8 + 2 * lc;
                *(float2*)&s_ts[row * P + col] =
                    make_float2(fmaxf(acc[mt][nt][0] + bv0, 0.f), fmaxf(acc[mt][nt][1] + bv0, 0.f));
                *(float2*)&s_ts[(row + 8) * P + col] =
                    make_float2(fmaxf(acc[mt][nt][2] + bv8, 0.f), fmaxf(acc[mt][nt][3] + bv8, 0.f));
            }
        }
    }
    __syncthreads();

    // ---- re-split relu(D1) -> s_rh/s_rl; stage w2 ----
    for (int e = tid; e < 8192; e += 256) {
        int o = e >> 6, j = e & 63;
        float2 v = *(const float2*)(w2g + o * 128 + 2 * j);
        uint32_t hi, lo; bfsplit2(v.x, v.y, hi, lo);
        s_wh[o * PX + j] = hi; s_wl[o * PX + j] = lo;
    }
    for (int it = w; it < 256; it += 8) {
        int cp = it >> 2, pos = (it & 3) * 32 + lane;
        float v0 = s_ts[(2 * cp) * P + pos];
        float v1 = s_ts[(2 * cp + 1) * P + pos];
        uint32_t hi, lo; bfsplit2(v0, v1, hi, lo);
        s_rh[pos * PX + cp] = hi; s_rl[pos * PX + cp] = lo;
    }
    __syncthreads();

    // ---- GEMM2: D[128][128] = w2 * relu(D1) ----
    {
        float acc[4][4][4];
#pragma unroll
        for (int mt = 0; mt < 4; mt++)
#pragma unroll
            for (int nt = 0; nt < 4; nt++)
#pragma unroll
                for (int r = 0; r < 4; r++) acc[mt][nt][r] = 0.f;
#pragma unroll 1
        for (int ks = 0; ks < 8; ks++) {
            const int kp = ks * 8 + lc;
            uint32_t ah[4][4], al[4][4], bh[4][2], bl[4][2];
#pragma unroll
            for (int mt = 0; mt < 4; mt++) {
                int r0 = (out0 + mt * 16 + lr) * PX + kp, r8 = r0 + 8 * PX;
                ah[mt][0] = s_wh[r0]; ah[mt][1] = s_wh[r8];
                ah[mt][2] = s_wh[r0 + 4]; ah[mt][3] = s_wh[r8 + 4];
                al[mt][0] = s_wl[r0]; al[mt][1] = s_wl[r8];
                al[mt][2] = s_wl[r0 + 4]; al[mt][3] = s_wl[r8 + 4];
            }
#pragma unroll
            for (int nt = 0; nt < 4; nt++) {
                int q = (pos0 + nt * 8 + lr) * PX + kp;
                bh[nt][0] = s_rh[q]; bh[nt][1] = s_rh[q + 4];
                bl[nt][0] = s_rl[q]; bl[nt][1] = s_rl[q + 4];
            }
#pragma unroll
            for (int mt = 0; mt < 4; mt++)
#pragma unroll
                for (int nt = 0; nt < 4; nt++) {
                    mma_bf16(acc[mt][nt], ah[mt], bh[nt]);
                    mma_bf16(acc[mt][nt], ah[mt], bl[nt]);
                    mma_bf16(acc[mt][nt], al[mt], bh[nt]);
                }
        }
#pragma unroll
        for (int mt = 0; mt < 4; mt++)
#pragma unroll
            for (int nt = 0; nt < 4; nt++) {
                int row = out0 + mt * 16 + lr;
                int col = pos0 + nt * 8 + 2 * lc;
                *(float2*)&s_ts[row * P + col] = make_float2(acc[mt][nt][0], acc[mt][nt][1]);
                *(float2*)&s_ts[(row + 8) * P + col] = make_float2(acc[mt][nt][2], acc[mt][nt][3]);
            }
    }
    __syncthreads();

    // ---- deterministic column sums over 128 positions ----
    {
        float* sred = (float*)s_rh;   // scratch reuse
        int c = tid & 127, half = tid >> 7;
        float sum = 0.f;
        for (int p = half * 64; p < half * 64 + 64; p++) sum += s_ts[c * P + p];
        sred[half * 128 + c] = sum;
        __syncthreads();
        if (tid < 128)
            partial[((size_t)b * 32 + blockIdx.x) * 128 + tid] =
                sred[tid] + sred[128 + tid] + 128.f * b2[tid];
    }
}

// ---------------------------------------------------------------------------
__global__ __launch_bounds__(256) void final_kernel(
    const float* __restrict__ partial,
    const float* __restrict__ wf1, const float* __restrict__ bf1,
    const float* __restrict__ wf2, const float* __restrict__ bf2,
    const float* __restrict__ wf3, const float* __restrict__ bf3,
    float* __restrict__ out)
{
    __shared__ float pooled[128];
    __shared__ float z1[256];
    __shared__ float z2[128];
    int b = blockIdx.x, tid = threadIdx.x;
    if (tid < 128) {
        float s = 0.f;
        for (int t = 0; t < 32; t++) s += partial[((size_t)b * 32 + t) * 128 + tid];
        pooled[tid] = s * (1.f / (float)LL);
    }
    __syncthreads();
    {
        float a = bf1[tid];
        for (int c = 0; c < 128; c++) a += wf1[tid * 128 + c] * pooled[c];
        z1[tid] = fmaxf(a, 0.f);
    }
    __syncthreads();
    if (tid < 128) {
        float a = bf2[tid];
        for (int c = 0; c < 256; c++) a += wf2[tid * 256 + c] * z1[c];
        z2[tid] = fmaxf(a, 0.f);
    }
    __syncthreads();
    if (tid < 6) {
        float a = bf3[tid];
        for (int c = 0; c < 128; c++) a += wf3[tid * 128 + c] * z2[c];
        out[b * 6 + tid] = a;
    }
}

// ---------------------------------------------------------------------------
extern "C" void kernel_launch(void* const* d_in, const int* in_sizes, int n_in,
                              void* d_out, int out_size)
{
    const float* x      = (const float*)d_in[0];
    const float* w_in   = (const float*)d_in[1];
    const float* b_in   = (const float*)d_in[2];
    const float* w_dil  = (const float*)d_in[3];
    const float* b_dil  = (const float*)d_in[4];
    const float* w_res  = (const float*)d_in[5];
    const float* b_res  = (const float*)d_in[6];
    const float* w_skip = (const float*)d_in[7];
    const float* b_skip = (const float*)d_in[8];
    const float* w_out1 = (const float*)d_in[9];
    const float* b_out1 = (const float*)d_in[10];
    const float* w_out2 = (const float*)d_in[11];
    const float* b_out2 = (const float*)d_in[12];
    const float* w_fc1  = (const float*)d_in[13];
    const float* b_fc1  = (const float*)d_in[14];
    const float* w_fc2  = (const float*)d_in[15];
    const float* b_fc2  = (const float*)d_in[16];
    const float* w_fc3  = (const float*)d_in[17];
    const float* b_fc3  = (const float*)d_in[18];
    float* out = (float*)d_out;

    float *h0, *h1, *skipb, *partial;
    cudaGetSymbolAddress((void**)&h0,      g_h0);
    cudaGetSymbolAddress((void**)&h1,      g_h1);
    cudaGetSymbolAddress((void**)&skipb,   g_skip);
    cudaGetSymbolAddress((void**)&partial, g_partial);

    const int SMEM = (128 * P + 4 * 128 * PX) * 4;   // 206,848 B
    cudaFuncSetAttribute(block_kernel, cudaFuncAttributeMaxDynamicSharedMemorySize, SMEM);
    cudaFuncSetAttribute(post_kernel,  cudaFuncAttributeMaxDynamicSharedMemorySize, SMEM);

    proj_kernel<<<(BB * LL * 64) / 256, 256>>>(x, w_in, b_in, h0);

    dim3 grid(LL / 128, BB);
    const float* hin = h0;
    float* hout = h1;
    for (int i = 0; i < NBLK; ++i) {
        int d = 1 << (i % 10);
        block_kernel<<<grid, 256, SMEM>>>(
            hin, hout, skipb,
            w_dil + (size_t)i * 128 * 64 * 2, b_dil + i * 128,
            w_res + (size_t)i * 64 * 64,      b_res + i * 64,
            w_skip + (size_t)i * 128 * 64,    b_skip + i * 128,
            d, (i == 0) ? 1 : 0);
        const float* t = hout;
        hout = (float*)hin;
        hin = t;
    }

    post_kernel<<<grid, 256, SMEM>>>(skipb, w_out1, b_out1, w_out2, b_out2, partial);
    final_kernel<<<BB, 256>>>(partial, w_fc1, b_fc1, w_fc2, b_fc2, w_fc3, b_fc3, out);
}

// round 8
// speedup vs baseline: 2.6719x; 1.3983x over previous
#include <cuda_runtime.h>
#include <cuda_bf16.h>
#include <math.h>
#include <stdint.h>

#define BB   64
#define LL   4096
#define RC   64
#define SC   128
#define NBLK 30
#define P    132    // fp32 staging pitch (floats)
#define PX   68     // pitch (words) for 64-pair split arrays (68 mod 32 == 4)
#define PG   36     // pitch (words) for 32-pair split arrays (36 mod 32 == 4)

// Static device scratch (allocation-free contract)
__device__ float g_h0[(size_t)BB * LL * RC];
__device__ float g_h1[(size_t)BB * LL * RC];
__device__ float g_skip[(size_t)BB * LL * SC];
__device__ float g_partial[(size_t)BB * 32 * SC];
// pre-split weights (bf16x2 hi/lo pair-words)
__device__ uint32_t g_wdh[NBLK * 8192], g_wdl[NBLK * 8192];   // conv  [o][64 pairs]
__device__ uint32_t g_wrh[NBLK * 2048], g_wrl[NBLK * 2048];   // res   [o][32 pairs]
__device__ uint32_t g_wsh[NBLK * 4096], g_wsl[NBLK * 4096];   // skip  [o][32 pairs]

// ---------------------------------------------------------------------------
__device__ __forceinline__ void bfsplit2(float v0, float v1, uint32_t& hi, uint32_t& lo) {
    __nv_bfloat16 h0 = __float2bfloat16_rn(v0);
    __nv_bfloat16 h1 = __float2bfloat16_rn(v1);
    float r0 = v0 - __bfloat162float(h0);
    float r1 = v1 - __bfloat162float(h1);
    __nv_bfloat16 l0 = __float2bfloat16_rn(r0);
    __nv_bfloat16 l1 = __float2bfloat16_rn(r1);
    hi = (uint32_t)__bfloat16_as_ushort(h0) | ((uint32_t)__bfloat16_as_ushort(h1) << 16);
    lo = (uint32_t)__bfloat16_as_ushort(l0) | ((uint32_t)__bfloat16_as_ushort(l1) << 16);
}

__device__ __forceinline__ void mma_bf16(float* d, const uint32_t* a, const uint32_t* b) {
    asm volatile(
        "mma.sync.aligned.m16n8k16.row.col.f32.bf16.bf16.f32 "
        "{%0,%1,%2,%3}, {%4,%5,%6,%7}, {%8,%9}, {%0,%1,%2,%3};"
        : "+f"(d[0]), "+f"(d[1]), "+f"(d[2]), "+f"(d[3])
        : "r"(a[0]), "r"(a[1]), "r"(a[2]), "r"(a[3]), "r"(b[0]), "r"(b[1]));
}

// ---------------------------------------------------------------------------
// Pre-split all layer weights into bf16 hi/lo pair-words (runs once per call).
// Pair j of a [rows][2*jp] fp32 matrix lives at float offset 2*j.
// ---------------------------------------------------------------------------
__global__ __launch_bounds__(256) void split_kernel(
    const float* __restrict__ wd, const float* __restrict__ wr,
    const float* __restrict__ ws)
{
    int id = blockIdx.x * 256 + threadIdx.x;
    if (id >= NBLK * 14336) return;
    int i = id / 14336, r = id % 14336;
    const float* src; uint32_t *dh, *dl; int off;
    if (r < 8192)       { src = wd + (size_t)i * 16384; off = r;        dh = g_wdh + i * 8192; dl = g_wdl + i * 8192; }
    else if (r < 10240) { src = wr + (size_t)i * 4096;  off = r - 8192; dh = g_wrh + i * 2048; dl = g_wrl + i * 2048; }
    else                { src = ws + (size_t)i * 8192;  off = r - 10240;dh = g_wsh + i * 4096; dl = g_wsl + i * 4096; }
    float2 v = *(const float2*)(src + 2 * off);
    uint32_t hi, lo; bfsplit2(v.x, v.y, hi, lo);
    dh[off] = hi; dl[off] = lo;
}

// ---------------------------------------------------------------------------
__global__ __launch_bounds__(256) void proj_kernel(
    const float* __restrict__ x, const float* __restrict__ w_in,
    const float* __restrict__ b_in, float* __restrict__ h)
{
    int idx = blockIdx.x * 256 + threadIdx.x;
    int oc = idx & 63;
    int l  = (idx >> 6) & (LL - 1);
    int b  = idx >> 18;
    float acc = b_in[oc];
#pragma unroll
    for (int c = 0; c < 8; ++c)
        acc += w_in[oc * 8 + c] * x[((size_t)(b * 8 + c)) * LL + l];
    h[(size_t)idx] = acc;
}

// ---------------------------------------------------------------------------
// One WaveNet block via 3xBF16 mma.sync. 512 threads (16 warps), 128 pos/CTA.
// Weights arrive pre-split from global; staging is pure uint4 copies.
// ---------------------------------------------------------------------------
__global__ __launch_bounds__(512, 1) void block_kernel(
    const float* __restrict__ h_in, float* __restrict__ h_out,
    float* __restrict__ skip,
    const uint32_t* __restrict__ wdh, const uint32_t* __restrict__ wdl,
    const float* __restrict__ bd,
    const uint32_t* __restrict__ wrh, const uint32_t* __restrict__ wrl,
    const float* __restrict__ br,
    const uint32_t* __restrict__ wsh, const uint32_t* __restrict__ wsl,
    const float* __restrict__ bs,
    int d, int first)
{
    extern __shared__ float sm[];
    float*    s_ts = sm;                            // [128][P] fp32 staging
    uint32_t* s_xh = (uint32_t*)(sm + 128 * P);     // [128 pos][PX] X hi pairs
    uint32_t* s_xl = s_xh + 128 * PX;
    uint32_t* s_wh = s_xl + 128 * PX;               // [128 o][PX] conv W hi
    uint32_t* s_wl = s_wh + 128 * PX;
    // overlays after conv:
    uint32_t* s_gh  = s_xh;                         // [128 pos][PG] gated G
    uint32_t* s_gl  = s_xl;
    uint32_t* s_wrh = s_wh;                         // [64 o][PG]
    uint32_t* s_wrl = s_wl;
    uint32_t* s_wsh = s_wh + 64 * PG;               // [128 o][PG]
    uint32_t* s_wsl = s_wl + 64 * PG;

    const int tid  = threadIdx.x;
    const int lane = tid & 31;
    const int w    = tid >> 5;      // warp 0..15
    const int lr   = lane >> 2;     // 0..7
    const int lc   = lane & 3;      // 0..3
    const int b    = blockIdx.y;
    const int l0   = blockIdx.x * 128;

    // ---- stage X split: pair (k=2c: delayed, k=2c+1: current) ----
    {
        int c = tid & 63, p0 = tid >> 6;
        const float* hb = h_in + (size_t)b * LL * 64;
#pragma unroll
        for (int p = p0; p < 128; p += 8) {
            int l = l0 + p, ld = l - d;
            float cur = hb[(size_t)l * 64 + c];
            float del = (ld >= 0) ? hb[(size_t)ld * 64 + c] : 0.f;
            uint32_t hi, lo; bfsplit2(del, cur, hi, lo);
            s_xh[p * PX + c] = hi; s_xl[p * PX + c] = lo;
        }
    }
    // ---- stage conv W (pre-split): 2048 uint4 pairs each for hi/lo ----
    for (int e = tid; e < 2048; e += 512) {
        int o = e >> 4, q = e & 15;
        *(uint4*)&s_wh[o * PX + q * 4] = ((const uint4*)wdh)[e];
        *(uint4*)&s_wl[o * PX + q * 4] = ((const uint4*)wdl)[e];
    }
    __syncthreads();

    // ================= conv GEMM: D[128 out][128 pos], K=128 =================
    {
        const int out0 = (w >> 2) * 32;
        const int pos0 = (w & 3) * 32;
        float acc[2][4][4];
#pragma unroll
        for (int mt = 0; mt < 2; mt++)
#pragma unroll
            for (int nt = 0; nt < 4; nt++)
#pragma unroll
                for (int r = 0; r < 4; r++) acc[mt][nt][r] = 0.f;

#pragma unroll 1
        for (int ks = 0; ks < 8; ks++) {
            const int kp = ks * 8 + lc;
            uint32_t ah[2][4], al[2][4], bh[4][2], bl[4][2];
#pragma unroll
            for (int mt = 0; mt < 2; mt++) {
                int r0 = (out0 + mt * 16 + lr) * PX + kp;
                int r8 = r0 + 8 * PX;
                ah[mt][0] = s_wh[r0]; ah[mt][1] = s_wh[r8];
                ah[mt][2] = s_wh[r0 + 4]; ah[mt][3] = s_wh[r8 + 4];
                al[mt][0] = s_wl[r0]; al[mt][1] = s_wl[r8];
                al[mt][2] = s_wl[r0 + 4]; al[mt][3] = s_wl[r8 + 4];
            }
#pragma unroll
            for (int nt = 0; nt < 4; nt++) {
                int q = (pos0 + nt * 8 + lr) * PX + kp;
                bh[nt][0] = s_xh[q]; bh[nt][1] = s_xh[q + 4];
                bl[nt][0] = s_xl[q]; bl[nt][1] = s_xl[q + 4];
            }
#pragma unroll
            for (int mt = 0; mt < 2; mt++)
#pragma unroll
                for (int nt = 0; nt < 4; nt++) {
                    mma_bf16(acc[mt][nt], ah[mt], bh[nt]);
                    mma_bf16(acc[mt][nt], ah[mt], bl[nt]);
                    mma_bf16(acc[mt][nt], al[mt], bh[nt]);
                }
        }
#pragma unroll
        for (int mt = 0; mt < 2; mt++)
#pragma unroll
            for (int nt = 0; nt < 4; nt++) {
                int row = out0 + mt * 16 + lr;
                int col = pos0 + nt * 8 + 2 * lc;
                *(float2*)&s_ts[row * P + col] = make_float2(acc[mt][nt][0], acc[mt][nt][1]);
                *(float2*)&s_ts[(row + 8) * P + col] = make_float2(acc[mt][nt][2], acc[mt][nt][3]);
            }
    }
    __syncthreads();

    // ---- stage wr/ws (pre-split) over conv-W region; gate -> G split ----
    for (int e = tid; e < 512; e += 512) {
        int o = e >> 3, q = e & 7;
        *(uint4*)&s_wrh[o * PG + q * 4] = ((const uint4*)wrh)[e];
        *(uint4*)&s_wrl[o * PG + q * 4] = ((const uint4*)wrl)[e];
    }
    for (int e = tid; e < 1024; e += 512) {
        int o = e >> 3, q = e & 7;
        *(uint4*)&s_wsh[o * PG + q * 4] = ((const uint4*)wsh)[e];
        *(uint4*)&s_wsl[o * PG + q * 4] = ((const uint4*)wsl)[e];
    }
    for (int it = w; it < 128; it += 16) {
        int cp = it >> 2, pos = (it & 3) * 32 + lane;
        int c0 = 2 * cp;
        float t0 = s_ts[c0 * P + pos] + bd[c0];
        float t1 = s_ts[(c0 + 1) * P + pos] + bd[c0 + 1];
        float sg0 = s_ts[(64 + c0) * P + pos] + bd[64 + c0];
        float sg1 = s_ts[(65 + c0) * P + pos] + bd[65 + c0];
        float g0 = (2.f * __fdividef(1.f, 1.f + __expf(-2.f * t0)) - 1.f) *
                   __fdividef(1.f, 1.f + __expf(-sg0));
        float g1 = (2.f * __fdividef(1.f, 1.f + __expf(-2.f * t1)) - 1.f) *
                   __fdividef(1.f, 1.f + __expf(-sg1));
        uint32_t hi, lo; bfsplit2(g0, g1, hi, lo);
        s_gh[pos * PG + cp] = hi; s_gl[pos * PG + cp] = lo;
    }
    __syncthreads();

    // ================= res GEMM: D[64][128] = wr * G, K=64 =================
    {
        const int o0  = (w & 3) * 16;
        const int pp0 = (w >> 2) * 32;
        float racc[4][4];
#pragma unroll
        for (int nt = 0; nt < 4; nt++)
#pragma unroll
            for (int r = 0; r < 4; r++) racc[nt][r] = 0.f;

#pragma unroll 1
        for (int ks = 0; ks < 4; ks++) {
            const int kp = ks * 8 + lc;
            uint32_t ah[4], al[4], bh[4][2], bl[4][2];
            int r0 = (o0 + lr) * PG + kp, r8 = r0 + 8 * PG;
            ah[0] = s_wrh[r0]; ah[1] = s_wrh[r8]; ah[2] = s_wrh[r0 + 4]; ah[3] = s_wrh[r8 + 4];
            al[0] = s_wrl[r0]; al[1] = s_wrl[r8]; al[2] = s_wrl[r0 + 4]; al[3] = s_wrl[r8 + 4];
#pragma unroll
            for (int nt = 0; nt < 4; nt++) {
                int q = (pp0 + nt * 8 + lr) * PG + kp;
                bh[nt][0] = s_gh[q]; bh[nt][1] = s_gh[q + 4];
                bl[nt][0] = s_gl[q]; bl[nt][1] = s_gl[q + 4];
            }
#pragma unroll
            for (int nt = 0; nt < 4; nt++) {
                mma_bf16(racc[nt], ah, bh[nt]);
                mma_bf16(racc[nt], ah, bl[nt]);
                mma_bf16(racc[nt], al, bh[nt]);
            }
        }
        float b0v = br[o0 + lr], b8v = br[o0 + lr + 8];
#pragma unroll
        for (int nt = 0; nt < 4; nt++) {
            int row = o0 + lr;
            int col = pp0 + nt * 8 + 2 * lc;
            *(float2*)&s_ts[row * P + col] = make_float2(racc[nt][0] + b0v, racc[nt][1] + b0v);
            *(float2*)&s_ts[(row + 8) * P + col] = make_float2(racc[nt][2] + b8v, racc[nt][3] + b8v);
        }
    }
    __syncthreads();

    // ---- h_out = res + residual(h_in), coalesced ----
    {
        int c = tid & 63, p0 = tid >> 6;
#pragma unroll
        for (int p = p0; p < 128; p += 8) {
            size_t gi = ((size_t)b * LL + l0 + p) * 64 + c;
            h_out[gi] = s_ts[c * P + p] + h_in[gi];
        }
    }
    __syncthreads();

    // ================= skip GEMM: D[128][128] = ws * G, K=64 =================
    {
        const int o0  = (w & 3) * 32;
        const int pp0 = (w >> 2) * 32;
        float sacc[2][4][4];
#pragma unroll
        for (int mt = 0; mt < 2; mt++)
#pragma unroll
            for (int nt = 0; nt < 4; nt++)
#pragma unroll
                for (int r = 0; r < 4; r++) sacc[mt][nt][r] = 0.f;

#pragma unroll 1
        for (int ks = 0; ks < 4; ks++) {
            const int kp = ks * 8 + lc;
            uint32_t ah[2][4], al[2][4], bh[4][2], bl[4][2];
#pragma unroll
            for (int mt = 0; mt < 2; mt++) {
                int r0 = (o0 + mt * 16 + lr) * PG + kp, r8 = r0 + 8 * PG;
                ah[mt][0] = s_wsh[r0]; ah[mt][1] = s_wsh[r8];
                ah[mt][2] = s_wsh[r0 + 4]; ah[mt][3] = s_wsh[r8 + 4];
                al[mt][0] = s_wsl[r0]; al[mt][1] = s_wsl[r8];
                al[mt][2] = s_wsl[r0 + 4]; al[mt][3] = s_wsl[r8 + 4];
            }
#pragma unroll
            for (int nt = 0; nt < 4; nt++) {
                int q = (pp0 + nt * 8 + lr) * PG + kp;
                bh[nt][0] = s_gh[q]; bh[nt][1] = s_gh[q + 4];
                bl[nt][0] = s_gl[q]; bl[nt][1] = s_gl[q + 4];
            }
#pragma unroll
            for (int mt = 0; mt < 2; mt++)
#pragma unroll
                for (int nt = 0; nt < 4; nt++) {
                    mma_bf16(sacc[mt][nt], ah[mt], bh[nt]);
                    mma_bf16(sacc[mt][nt], ah[mt], bl[nt]);
                    mma_bf16(sacc[mt][nt], al[mt], bh[nt]);
                }
        }
#pragma unroll
        for (int mt = 0; mt < 2; mt++)
#pragma unroll
            for (int nt = 0; nt < 4; nt++) {
                int row = o0 + mt * 16 + lr;
                int col = pp0 + nt * 8 + 2 * lc;
                *(float2*)&s_ts[row * P + col] = make_float2(sacc[mt][nt][0], sacc[mt][nt][1]);
                *(float2*)&s_ts[(row + 8) * P + col] = make_float2(sacc[mt][nt][2], sacc[mt][nt][3]);
            }
    }
    __syncthreads();

    // ---- coalesced skip RMW ----
    {
        int s = tid & 127, pr = tid >> 7;
        float bsv = bs[s];
#pragma unroll
        for (int p = pr; p < 128; p += 4) {
            size_t gi = ((size_t)b * LL + l0 + p) * 128 + s;
            float v = s_ts[s * P + p] + bsv;
            if (!first) v += skip[gi];
            skip[gi] = v;
        }
    }
}

// ---------------------------------------------------------------------------
// Post: relu(skip) -> out1 -> relu -> out2 -> per-tile column sums (bf16 mma)
// ---------------------------------------------------------------------------
__global__ __launch_bounds__(256) void post_kernel(
    const float* __restrict__ skip,
    const float* __restrict__ w1g, const float* __restrict__ b1,
    const float* __restrict__ w2g, const float* __restrict__ b2,
    float* __restrict__ partial)
{
    extern __shared__ float sm[];
    float*    s_ts = sm;                          // [128][P] fp32 staging
    uint32_t* s_rh = (uint32_t*)(sm + 128 * P);   // [128 pos][PX] act hi pairs
    uint32_t* s_rl = s_rh + 128 * PX;
    uint32_t* s_wh = s_rl + 128 * PX;             // [128 o][PX] weight hi pairs
    uint32_t* s_wl = s_wh + 128 * PX;

    const int tid  = threadIdx.x;
    const int lane = tid & 31;
    const int w    = tid >> 5;
    const int lr   = lane >> 2;
    const int lc   = lane & 3;
    const int b    = blockIdx.y;
    const int l0   = blockIdx.x * 128;

    const int out0 = (w >> 2) * 64;
    const int pos0 = (w & 3) * 32;

    {
        int cp = tid & 63, p0 = tid >> 6;
#pragma unroll
        for (int p = p0; p < 128; p += 4) {
            float2 v = *(const float2*)(skip + ((size_t)b * LL + l0 + p) * 128 + 2 * cp);
            v.x = fmaxf(v.x, 0.f); v.y = fmaxf(v.y, 0.f);
            uint32_t hi, lo; bfsplit2(v.x, v.y, hi, lo);
            s_rh[p * PX + cp] = hi; s_rl[p * PX + cp] = lo;
        }
    }
    for (int e = tid; e < 8192; e += 256) {
        int o = e >> 6, j = e & 63;
        float2 v = *(const float2*)(w1g + o * 128 + 2 * j);
        uint32_t hi, lo; bfsplit2(v.x, v.y, hi, lo);
        s_wh[o * PX + j] = hi; s_wl[o * PX + j] = lo;
    }
    __syncthreads();

    {
        float acc[4][4][4];
#pragma unroll
        for (int mt = 0; mt < 4; mt++)
#pragma unroll
            for (int nt = 0; nt < 4; nt++)
#pragma unroll
                for (int r = 0; r < 4; r++) acc[mt][nt][r] = 0.f;
#pragma unroll 1
        for (int ks = 0; ks < 8; ks++) {
            const int kp = ks * 8 + lc;
            uint32_t ah[4][4], al[4][4], bh[4][2], bl[4][2];
#pragma unroll
            for (int mt = 0; mt < 4; mt++) {
                int r0 = (out0 + mt * 16 + lr) * PX + kp, r8 = r0 + 8 * PX;
                ah[mt][0] = s_wh[r0]; ah[mt][1] = s_wh[r8];
                ah[mt][2] = s_wh[r0 + 4]; ah[mt][3] = s_wh[r8 + 4];
                al[mt][0] = s_wl[r0]; al[mt][1] = s_wl[r8];
                al[mt][2] = s_wl[r0 + 4]; al[mt][3] = s_wl[r8 + 4];
            }
#pragma unroll
            for (int nt = 0; nt < 4; nt++) {
                int q = (pos0 + nt * 8 + lr) * PX + kp;
                bh[nt][0] = s_rh[q]; bh[nt][1] = s_rh[q + 4];
                bl[nt][0] = s_rl[q]; bl[nt][1] = s_rl[q + 4];
            }
#pragma unroll
            for (int mt = 0; mt < 4; mt++)
#pragma unroll
                for (int nt = 0; nt < 4; nt++) {
                    mma_bf16(acc[mt][nt], ah[mt], bh[nt]);
                    mma_bf16(acc[mt][nt], ah[mt], bl[nt]);
                    mma_bf16(acc[mt][nt], al[mt], bh[nt]);
                }
        }
#pragma unroll
        for (int mt = 0; mt < 4; mt++) {
            int row = out0 + mt * 16 + lr;
            float bv0 = b1[row], bv8 = b1[row + 8];
#pragma unroll
            for (int nt = 0; nt < 4; nt++) {
                int col = pos0 + nt * 8 + 2 * lc;
                *(float2*)&s_ts[row * P + col] =
                    make_float2(fmaxf(acc[mt][nt][0] + bv0, 0.f), fmaxf(acc[mt][nt][1] + bv0, 0.f));
                *(float2*)&s_ts[(row + 8) * P + col] =
                    make_float2(fmaxf(acc[mt][nt][2] + bv8, 0.f), fmaxf(acc[mt][nt][3] + bv8, 0.f));
            }
        }
    }
    __syncthreads();

    for (int e = tid; e < 8192; e += 256) {
        int o = e >> 6, j = e & 63;
        float2 v = *(const float2*)(w2g + o * 128 + 2 * j);
        uint32_t hi, lo; bfsplit2(v.x, v.y, hi, lo);
        s_wh[o * PX + j] = hi; s_wl[o * PX + j] = lo;
    }
    for (int it = w; it < 256; it += 8) {
        int cp = it >> 2, pos = (it & 3) * 32 + lane;
        float v0 = s_ts[(2 * cp) * P + pos];
        float v1 = s_ts[(2 * cp + 1) * P + pos];
        uint32_t hi, lo; bfsplit2(v0, v1, hi, lo);
        s_rh[pos * PX + cp] = hi; s_rl[pos * PX + cp] = lo;
    }
    __syncthreads();

    {
        float acc[4][4][4];
#pragma unroll
        for (int mt = 0; mt < 4; mt++)
#pragma unroll
            for (int nt = 0; nt < 4; nt++)
#pragma unroll
                for (int r = 0; r < 4; r++) acc[mt][nt][r] = 0.f;
#pragma unroll 1
        for (int ks = 0; ks < 8; ks++) {
            const int kp = ks * 8 + lc;
            uint32_t ah[4][4], al[4][4], bh[4][2], bl[4][2];
#pragma unroll
            for (int mt = 0; mt < 4; mt++) {
                int r0 = (out0 + mt * 16 + lr) * PX + kp, r8 = r0 + 8 * PX;
                ah[mt][0] = s_wh[r0]; ah[mt][1] = s_wh[r8];
                ah[mt][2] = s_wh[r0 + 4]; ah[mt][3] = s_wh[r8 + 4];
                al[mt][0] = s_wl[r0]; al[mt][1] = s_wl[r8];
                al[mt][2] = s_wl[r0 + 4]; al[mt][3] = s_wl[r8 + 4];
            }
#pragma unroll
            for (int nt = 0; nt < 4; nt++) {
                int q = (pos0 + nt * 8 + lr) * PX + kp;
                bh[nt][0] = s_rh[q]; bh[nt][1] = s_rh[q + 4];
                bl[nt][0] = s_rl[q]; bl[nt][1] = s_rl[q + 4];
            }
#pragma unroll
            for (int mt = 0; mt < 4; mt++)
#pragma unroll
                for (int nt = 0; nt < 4; nt++) {
                    mma_bf16(acc[mt][nt], ah[mt], bh[nt]);
                    mma_bf16(acc[mt][nt], ah[mt], bl[nt]);
                    mma_bf16(acc[mt][nt], al[mt], bh[nt]);
                }
        }
#pragma unroll
        for (int mt = 0; mt < 4; mt++)
#pragma unroll
            for (int nt = 0; nt < 4; nt++) {
                int row = out0 + mt * 16 + lr;
                int col = pos0 + nt * 8 + 2 * lc;
                *(float2*)&s_ts[row * P + col] = make_float2(acc[mt][nt][0], acc[mt][nt][1]);
                *(float2*)&s_ts[(row + 8) * P + col] = make_float2(acc[mt][nt][2], acc[mt][nt][3]);
            }
    }
    __syncthreads();

    {
        float* sred = (float*)s_rh;
        int c = tid & 127, half = tid >> 7;
        float sum = 0.f;
        for (int p = half * 64; p < half * 64 + 64; p++) sum += s_ts[c * P + p];
        sred[half * 128 + c] = sum;
        __syncthreads();
        if (tid < 128)
            partial[((size_t)b * 32 + blockIdx.x) * 128 + tid] =
                sred[tid] + sred[128 + tid] + 128.f * b2[tid];
    }
}

// ---------------------------------------------------------------------------
__global__ __launch_bounds__(256) void final_kernel(
    const float* __restrict__ partial,
    const float* __restrict__ wf1, const float* __restrict__ bf1,
    const float* __restrict__ wf2, const float* __restrict__ bf2,
    const float* __restrict__ wf3, const float* __restrict__ bf3,
    float* __restrict__ out)
{
    __shared__ float pooled[128];
    __shared__ float z1[256];
    __shared__ float z2[128];
    int b = blockIdx.x, tid = threadIdx.x;
    if (tid < 128) {
        float s = 0.f;
        for (int t = 0; t < 32; t++) s += partial[((size_t)b * 32 + t) * 128 + tid];
        pooled[tid] = s * (1.f / (float)LL);
    }
    __syncthreads();
    {
        float a = bf1[tid];
        for (int c = 0; c < 128; c++) a += wf1[tid * 128 + c] * pooled[c];
        z1[tid] = fmaxf(a, 0.f);
    }
    __syncthreads();
    if (tid < 128) {
        float a = bf2[tid];
        for (int c = 0; c < 256; c++) a += wf2[tid * 256 + c] * z1[c];
        z2[tid] = fmaxf(a, 0.f);
    }
    __syncthreads();
    if (tid < 6) {
        float a = bf3[tid];
        for (int c = 0; c < 128; c++) a += wf3[tid * 128 + c] * z2[c];
        out[b * 6 + tid] = a;
    }
}

// ---------------------------------------------------------------------------
extern "C" void kernel_launch(void* const* d_in, const int* in_sizes, int n_in,
                              void* d_out, int out_size)
{
    const float* x      = (const float*)d_in[0];
    const float* w_in   = (const float*)d_in[1];
    const float* b_in   = (const float*)d_in[2];
    const float* w_dil  = (const float*)d_in[3];
    const float* b_dil  = (const float*)d_in[4];
    const float* w_res  = (const float*)d_in[5];
    const float* b_res  = (const float*)d_in[6];
    const float* w_skip = (const float*)d_in[7];
    const float* b_skip = (const float*)d_in[8];
    const float* w_out1 = (const float*)d_in[9];
    const float* b_out1 = (const float*)d_in[10];
    const float* w_out2 = (const float*)d_in[11];
    const float* b_out2 = (const float*)d_in[12];
    const float* w_fc1  = (const float*)d_in[13];
    const float* b_fc1  = (const float*)d_in[14];
    const float* w_fc2  = (const float*)d_in[15];
    const float* b_fc2  = (const float*)d_in[16];
    const float* w_fc3  = (const float*)d_in[17];
    const float* b_fc3  = (const float*)d_in[18];
    float* out = (float*)d_out;

    float *h0, *h1, *skipb, *partial;
    uint32_t *wdh, *wdl, *wrh, *wrl, *wsh, *wsl;
    cudaGetSymbolAddress((void**)&h0,      g_h0);
    cudaGetSymbolAddress((void**)&h1,      g_h1);
    cudaGetSymbolAddress((void**)&skipb,   g_skip);
    cudaGetSymbolAddress((void**)&partial, g_partial);
    cudaGetSymbolAddress((void**)&wdh,     g_wdh);
    cudaGetSymbolAddress((void**)&wdl,     g_wdl);
    cudaGetSymbolAddress((void**)&wrh,     g_wrh);
    cudaGetSymbolAddress((void**)&wrl,     g_wrl);
    cudaGetSymbolAddress((void**)&wsh,     g_wsh);
    cudaGetSymbolAddress((void**)&wsl,     g_wsl);

    const int SMEM = (128 * P + 4 * 128 * PX) * 4;   // 206,848 B
    cudaFuncSetAttribute(block_kernel, cudaFuncAttributeMaxDynamicSharedMemorySize, SMEM);
    cudaFuncSetAttribute(post_kernel,  cudaFuncAttributeMaxDynamicSharedMemorySize, SMEM);

    split_kernel<<<(NBLK * 14336 + 255) / 256, 256>>>(w_dil, w_res, w_skip);
    proj_kernel<<<(BB * LL * 64) / 256, 256>>>(x, w_in, b_in, h0);

    dim3 grid(LL / 128, BB);
    const float* hin = h0;
    float* hout = h1;
    for (int i = 0; i < NBLK; ++i) {
        int d = 1 << (i % 10);
        block_kernel<<<grid, 512, SMEM>>>(
            hin, hout, skipb,
            wdh + i * 8192, wdl + i * 8192, b_dil + i * 128,
            wrh + i * 2048, wrl + i * 2048, b_res + i * 64,
            wsh + i * 4096, wsl + i * 4096, b_skip + i * 128,
            d, (i == 0) ? 1 : 0);
        const float* t = hout;
        hout = (float*)hin;
        hin = t;
    }

    post_kernel<<<grid, 256, SMEM>>>(skipb, w_out1, b_out1, w_out2, b_out2, partial);
    final_kernel<<<BB, 256>>>(partial, w_fc1, b_fc1, w_fc2, b_fc2, w_fc3, b_fc3, out);
}